// round 10
// baseline (speedup 1.0000x reference)
#include <cuda_runtime.h>

#define NAT 10000
#define NN 32
#define RSN 16
#define THETAN 8
#define NEMB 4
#define FEAT 576           // 64 radial + 512 angular
#define PI_F 3.14159265358979f
#define RCUT 5.0f

__device__ float g_eatom[NAT];

__global__ void __launch_bounds__(128, 4) atom_kernel(
    const float* __restrict__ pos,   // [NAT,3]
    const float* __restrict__ spe,   // [NAT,4]
    const float* __restrict__ theta, // [8]
    const float* __restrict__ kn,    // [1]
    const float* __restrict__ W1,    // [576,64]
    const float* __restrict__ b1,    // [64]
    const float* __restrict__ W2,    // [64,64]
    const float* __restrict__ b2,    // [64]
    const float* __restrict__ W3,    // [64,1]
    const float* __restrict__ b3,    // [1]
    const int*   __restrict__ nbr)   // [NAT,32]
{
    __shared__ float ux[NN], uy[NN], uz[NN];
    __shared__ float rn_s[NN], fc_s[NN];
    __shared__ float semb_s[NN][NEMB];
    __shared__ __align__(16) float P_s[NN][64];
    __shared__ __align__(16) float A_s[NN * NN * 8];   // [ (j*32+k)*8 + t ], upper triangle (k>=j) only
    __shared__ float ct_s[8], st_s[8];
    __shared__ float desc_s[FEAT];
    __shared__ float h1p[2][64];
    __shared__ float h1_s[64], h2_s[64];
    __shared__ float posi[3], spei[4];

    const int i   = blockIdx.x;
    const int tid = threadIdx.x;

    if (tid < 3)  posi[tid] = pos[i * 3 + tid];
    if (tid >= 4 && tid < 8) spei[tid - 4] = spe[i * 4 + (tid - 4)];
    if (tid >= 8 && tid < 16) {
        float th = theta[tid - 8];
        ct_s[tid - 8] = cosf(th);
        st_s[tid - 8] = sinf(th);
    }
    for (int f = tid; f < FEAT; f += 128) desc_s[f] = 0.0f;
    __syncthreads();

    const float knv = kn[0];

    // ---- per-bond geometry, cutoff, species product ----
    if (tid < NN) {
        const int j = tid;
        const int n = nbr[i * NN + j];
        float dx = pos[n * 3 + 0] - posi[0];
        float dy = pos[n * 3 + 1] - posi[1];
        float dz = pos[n * 3 + 2] - posi[2];
        float r  = sqrtf(dx * dx + dy * dy + dz * dz) + 1e-8f;
        rn_s[j] = r;
        float inv = 1.0f / r;
        ux[j] = dx * inv; uy[j] = dy * inv; uz[j] = dz * inv;
        float fc = (r < RCUT) ? 0.5f * (cosf(PI_F * r / RCUT) + 1.0f) : 0.0f;
        fc_s[j] = fc;
        #pragma unroll
        for (int m = 0; m < 4; m++) semb_s[j][m] = spe[n * 4 + m] * spei[m];
    }
    __syncthreads();

    // ---- P[j][p] = bessel_l(r_j) * semb_m, p = l*4+m. 128 threads: j = tid%32, l-group = tid/32 ----
    {
        const int j  = tid & 31;
        const int lg = tid >> 5;
        const float r    = rn_s[j];
        const float coef = sqrtf(2.0f / RCUT) * fc_s[j] / r;
        const float a0   = (PI_F / RCUT) * knv * r;
        const float s0 = semb_s[j][0], s1 = semb_s[j][1], s2 = semb_s[j][2], s3 = semb_s[j][3];
        #pragma unroll
        for (int li = 0; li < 4; li++) {
            const int l = lg * 4 + li;
            const float bfl = coef * sinf(a0 * (float)(l + 1));
            P_s[j][l * 4 + 0] = bfl * s0;
            P_s[j][l * 4 + 1] = bfl * s1;
            P_s[j][l * 4 + 2] = bfl * s2;
            P_s[j][l * 4 + 3] = bfl * s3;
        }
    }
    __syncthreads();

    // ---- angular weights A_t[j,k] for k >= j ----
    {
        const float pref = 3.0517578125e-5f;  // 2^(1-16)
        for (int pi = tid; pi < NN * NN; pi += 128) {
            const int j = pi >> 5, k = pi & 31;
            if (k < j) continue;
            float c = ux[j] * ux[k] + uy[j] * uy[k] + uz[j] * uz[k];
            c = fminf(fmaxf(c, -0.999999f), 0.999999f);
            const float s = sqrtf(1.0f - c * c);
            float* a = &A_s[pi * 8];
            #pragma unroll
            for (int t = 0; t < 8; t++) {
                const float x  = 1.0f + c * ct_s[t] + s * st_s[t];
                const float x2 = x * x, x4 = x2 * x2, x8 = x4 * x4;
                a[t] = pref * (x8 * x8);
            }
        }
    }
    __syncthreads();

    // ---- angular descriptor: ang[t][p] = sum_{j,k} A_t[j,k] P[j,p] P[k,p]
    //      = diag + 2 * (k>j) part.  thread = (p = tid&63, parity half = tid>>6) ----
    {
        const int p   = tid & 63;
        const int par = tid >> 6;
        float offd[8] = {0, 0, 0, 0, 0, 0, 0, 0};
        float diag[8] = {0, 0, 0, 0, 0, 0, 0, 0};
        for (int j = par; j < NN; j += 2) {
            const float Pj  = P_s[j][p];
            const float Pj2 = Pj * Pj;
            const float4* ad = (const float4*)&A_s[(j * 32 + j) * 8];
            float4 d0 = ad[0], d1 = ad[1];
            diag[0] += d0.x * Pj2; diag[1] += d0.y * Pj2; diag[2] += d0.z * Pj2; diag[3] += d0.w * Pj2;
            diag[4] += d1.x * Pj2; diag[5] += d1.y * Pj2; diag[6] += d1.z * Pj2; diag[7] += d1.w * Pj2;
            #pragma unroll 2
            for (int k = j + 1; k < NN; k++) {
                const float q = Pj * P_s[k][p];
                const float4* aa = (const float4*)&A_s[(j * 32 + k) * 8];
                float4 a0 = aa[0], a1 = aa[1];
                offd[0] += a0.x * q; offd[1] += a0.y * q; offd[2] += a0.z * q; offd[3] += a0.w * q;
                offd[4] += a1.x * q; offd[5] += a1.y * q; offd[6] += a1.z * q; offd[7] += a1.w * q;
            }
        }
        #pragma unroll
        for (int t = 0; t < 8; t++)
            atomicAdd(&desc_s[64 + t * 64 + p], diag[t] + 2.0f * offd[t]);

        // radial descriptor: desc_rad[p] = sum_j P[j][p]
        if (par == 0) {
            float acc = 0.0f;
            #pragma unroll
            for (int j = 0; j < NN; j++) acc += P_s[j][p];
            desc_s[p] = acc;
        }
    }
    __syncthreads();

    // ---- MLP: h1 = tanh(desc @ W1 + b1) ----
    {
        const int o = tid & 63, seg = tid >> 6;
        float acc = 0.0f;
        const int f0 = seg * (FEAT / 2), f1 = f0 + (FEAT / 2);
        for (int f = f0; f < f1; f++)
            acc += desc_s[f] * __ldg(&W1[f * 64 + o]);
        h1p[seg][o] = acc;
    }
    __syncthreads();
    if (tid < 64)
        h1_s[tid] = tanhf(h1p[0][tid] + h1p[1][tid] + b1[tid]);
    __syncthreads();
    if (tid < 64) {
        float acc = b2[tid];
        #pragma unroll 8
        for (int f = 0; f < 64; f++) acc += h1_s[f] * __ldg(&W2[f * 64 + tid]);
        h2_s[tid] = tanhf(acc);
    }
    __syncthreads();
    if (tid == 0) {
        float acc = b3[0];
        #pragma unroll 8
        for (int f = 0; f < 64; f++) acc += h2_s[f] * __ldg(&W3[f]);
        g_eatom[i] = acc;
    }
}

// Deterministic fixed-order reduction (double accumulation, tree reduce).
__global__ void __launch_bounds__(256) reduce_kernel(float* __restrict__ out)
{
    __shared__ double red[256];
    const int tid = threadIdx.x;
    double acc = 0.0;
    for (int i = tid; i < NAT; i += 256) acc += (double)g_eatom[i];
    red[tid] = acc;
    __syncthreads();
    for (int s = 128; s > 0; s >>= 1) {
        if (tid < s) red[tid] += red[tid + s];
        __syncthreads();
    }
    if (tid == 0) out[0] = (float)red[0];
}

extern "C" void kernel_launch(void* const* d_in, const int* in_sizes, int n_in,
                              void* d_out, int out_size)
{
    const float* pos   = (const float*)d_in[0];
    const float* spe   = (const float*)d_in[1];
    const float* theta = (const float*)d_in[2];
    const float* kn    = (const float*)d_in[3];
    const float* W1    = (const float*)d_in[4];
    const float* b1    = (const float*)d_in[5];
    const float* W2    = (const float*)d_in[6];
    const float* b2    = (const float*)d_in[7];
    const float* W3    = (const float*)d_in[8];
    const float* b3    = (const float*)d_in[9];
    const int*   nbr   = (const int*)d_in[10];

    atom_kernel<<<NAT, 128>>>(pos, spe, theta, kn, W1, b1, W2, b2, W3, b3, nbr);
    reduce_kernel<<<1, 256>>>((float*)d_out);
}

// round 11
// speedup vs baseline: 1.0001x; 1.0001x over previous
#include <cuda_runtime.h>

#define NAT 10000
#define NN 32
#define RSN 16
#define THETAN 8
#define NEMB 4
#define FEAT 576           // 64 radial + 512 angular
#define PI_F 3.14159265358979f
#define RCUT 5.0f

__device__ float g_eatom[NAT];

__global__ void __launch_bounds__(128, 4) atom_kernel(
    const float* __restrict__ pos,   // [NAT,3]
    const float* __restrict__ spe,   // [NAT,4]
    const float* __restrict__ theta, // [8]
    const float* __restrict__ kn,    // [1]
    const float* __restrict__ W1,    // [576,64]
    const float* __restrict__ b1,    // [64]
    const float* __restrict__ W2,    // [64,64]
    const float* __restrict__ b2,    // [64]
    const float* __restrict__ W3,    // [64,1]
    const float* __restrict__ b3,    // [1]
    const int*   __restrict__ nbr)   // [NAT,32]
{
    __shared__ float ux[NN], uy[NN], uz[NN];
    __shared__ float rn_s[NN], fc_s[NN];
    __shared__ float semb_s[NN][NEMB];
    __shared__ __align__(16) float P_s[NN][64];
    __shared__ __align__(16) float A_s[NN * NN * 8];   // [ (j*32+k)*8 + t ], upper triangle (k>=j) only
    __shared__ float ct_s[8], st_s[8];
    __shared__ float desc_s[FEAT];
    __shared__ float h1p[2][64];
    __shared__ float h1_s[64], h2_s[64];
    __shared__ float posi[3], spei[4];

    const int i   = blockIdx.x;
    const int tid = threadIdx.x;

    if (tid < 3)  posi[tid] = pos[i * 3 + tid];
    if (tid >= 4 && tid < 8) spei[tid - 4] = spe[i * 4 + (tid - 4)];
    if (tid >= 8 && tid < 16) {
        float th = theta[tid - 8];
        ct_s[tid - 8] = cosf(th);
        st_s[tid - 8] = sinf(th);
    }
    for (int f = tid; f < FEAT; f += 128) desc_s[f] = 0.0f;
    __syncthreads();

    const float knv = kn[0];

    // ---- per-bond geometry, cutoff, species product ----
    if (tid < NN) {
        const int j = tid;
        const int n = nbr[i * NN + j];
        float dx = pos[n * 3 + 0] - posi[0];
        float dy = pos[n * 3 + 1] - posi[1];
        float dz = pos[n * 3 + 2] - posi[2];
        float r  = sqrtf(dx * dx + dy * dy + dz * dz) + 1e-8f;
        rn_s[j] = r;
        float inv = 1.0f / r;
        ux[j] = dx * inv; uy[j] = dy * inv; uz[j] = dz * inv;
        float fc = (r < RCUT) ? 0.5f * (cosf(PI_F * r / RCUT) + 1.0f) : 0.0f;
        fc_s[j] = fc;
        #pragma unroll
        for (int m = 0; m < 4; m++) semb_s[j][m] = spe[n * 4 + m] * spei[m];
    }
    __syncthreads();

    // ---- P[j][p] = bessel_l(r_j) * semb_m, p = l*4+m. 128 threads: j = tid%32, l-group = tid/32 ----
    {
        const int j  = tid & 31;
        const int lg = tid >> 5;
        const float r    = rn_s[j];
        const float coef = sqrtf(2.0f / RCUT) * fc_s[j] / r;
        const float a0   = (PI_F / RCUT) * knv * r;
        const float s0 = semb_s[j][0], s1 = semb_s[j][1], s2 = semb_s[j][2], s3 = semb_s[j][3];
        #pragma unroll
        for (int li = 0; li < 4; li++) {
            const int l = lg * 4 + li;
            const float bfl = coef * sinf(a0 * (float)(l + 1));
            P_s[j][l * 4 + 0] = bfl * s0;
            P_s[j][l * 4 + 1] = bfl * s1;
            P_s[j][l * 4 + 2] = bfl * s2;
            P_s[j][l * 4 + 3] = bfl * s3;
        }
    }
    __syncthreads();

    // ---- angular weights A_t[j,k] for k >= j ----
    {
        const float pref = 3.0517578125e-5f;  // 2^(1-16)
        for (int pi = tid; pi < NN * NN; pi += 128) {
            const int j = pi >> 5, k = pi & 31;
            if (k < j) continue;
            float c = ux[j] * ux[k] + uy[j] * uy[k] + uz[j] * uz[k];
            c = fminf(fmaxf(c, -0.999999f), 0.999999f);
            const float s = sqrtf(1.0f - c * c);
            float* a = &A_s[pi * 8];
            #pragma unroll
            for (int t = 0; t < 8; t++) {
                const float x  = 1.0f + c * ct_s[t] + s * st_s[t];
                const float x2 = x * x, x4 = x2 * x2, x8 = x4 * x4;
                a[t] = pref * (x8 * x8);
            }
        }
    }
    __syncthreads();

    // ---- angular descriptor: ang[t][p] = sum_{j,k} A_t[j,k] P[j,p] P[k,p]
    //      = diag + 2 * (k>j) part.  thread = (p = tid&63, parity half = tid>>6) ----
    {
        const int p   = tid & 63;
        const int par = tid >> 6;
        float offd[8] = {0, 0, 0, 0, 0, 0, 0, 0};
        float diag[8] = {0, 0, 0, 0, 0, 0, 0, 0};
        for (int j = par; j < NN; j += 2) {
            const float Pj  = P_s[j][p];
            const float Pj2 = Pj * Pj;
            const float4* ad = (const float4*)&A_s[(j * 32 + j) * 8];
            float4 d0 = ad[0], d1 = ad[1];
            diag[0] += d0.x * Pj2; diag[1] += d0.y * Pj2; diag[2] += d0.z * Pj2; diag[3] += d0.w * Pj2;
            diag[4] += d1.x * Pj2; diag[5] += d1.y * Pj2; diag[6] += d1.z * Pj2; diag[7] += d1.w * Pj2;
            #pragma unroll 2
            for (int k = j + 1; k < NN; k++) {
                const float q = Pj * P_s[k][p];
                const float4* aa = (const float4*)&A_s[(j * 32 + k) * 8];
                float4 a0 = aa[0], a1 = aa[1];
                offd[0] += a0.x * q; offd[1] += a0.y * q; offd[2] += a0.z * q; offd[3] += a0.w * q;
                offd[4] += a1.x * q; offd[5] += a1.y * q; offd[6] += a1.z * q; offd[7] += a1.w * q;
            }
        }
        #pragma unroll
        for (int t = 0; t < 8; t++)
            atomicAdd(&desc_s[64 + t * 64 + p], diag[t] + 2.0f * offd[t]);

        // radial descriptor: desc_rad[p] = sum_j P[j][p]
        if (par == 0) {
            float acc = 0.0f;
            #pragma unroll
            for (int j = 0; j < NN; j++) acc += P_s[j][p];
            desc_s[p] = acc;
        }
    }
    __syncthreads();

    // ---- MLP: h1 = tanh(desc @ W1 + b1) ----
    {
        const int o = tid & 63, seg = tid >> 6;
        float acc = 0.0f;
        const int f0 = seg * (FEAT / 2), f1 = f0 + (FEAT / 2);
        for (int f = f0; f < f1; f++)
            acc += desc_s[f] * __ldg(&W1[f * 64 + o]);
        h1p[seg][o] = acc;
    }
    __syncthreads();
    if (tid < 64)
        h1_s[tid] = tanhf(h1p[0][tid] + h1p[1][tid] + b1[tid]);
    __syncthreads();
    if (tid < 64) {
        float acc = b2[tid];
        #pragma unroll 8
        for (int f = 0; f < 64; f++) acc += h1_s[f] * __ldg(&W2[f * 64 + tid]);
        h2_s[tid] = tanhf(acc);
    }
    __syncthreads();
    if (tid == 0) {
        float acc = b3[0];
        #pragma unroll 8
        for (int f = 0; f < 64; f++) acc += h2_s[f] * __ldg(&W3[f]);
        g_eatom[i] = acc;
    }
}

// Deterministic fixed-order reduction (double accumulation, tree reduce).
__global__ void __launch_bounds__(256) reduce_kernel(float* __restrict__ out)
{
    __shared__ double red[256];
    const int tid = threadIdx.x;
    double acc = 0.0;
    for (int i = tid; i < NAT; i += 256) acc += (double)g_eatom[i];
    red[tid] = acc;
    __syncthreads();
    for (int s = 128; s > 0; s >>= 1) {
        if (tid < s) red[tid] += red[tid + s];
        __syncthreads();
    }
    if (tid == 0) out[0] = (float)red[0];
}

extern "C" void kernel_launch(void* const* d_in, const int* in_sizes, int n_in,
                              void* d_out, int out_size)
{
    const float* pos   = (const float*)d_in[0];
    const float* spe   = (const float*)d_in[1];
    const float* theta = (const float*)d_in[2];
    const float* kn    = (const float*)d_in[3];
    const float* W1    = (const float*)d_in[4];
    const float* b1    = (const float*)d_in[5];
    const float* W2    = (const float*)d_in[6];
    const float* b2    = (const float*)d_in[7];
    const float* W3    = (const float*)d_in[8];
    const float* b3    = (const float*)d_in[9];
    const int*   nbr   = (const int*)d_in[10];

    atom_kernel<<<NAT, 128>>>(pos, spe, theta, kn, W1, b1, W2, b2, W3, b3, nbr);
    reduce_kernel<<<1, 256>>>((float*)d_out);
}

// round 12
// speedup vs baseline: 1.1790x; 1.1789x over previous
#include <cuda_runtime.h>

#define NAT 10000
#define NN 32
#define RSN 16
#define THETAN 8
#define NEMB 4
#define FEAT 576           // 64 radial + 512 angular
#define PI_F 3.14159265358979f
#define RCUT 5.0f

__device__ float g_eatom[NAT];
__device__ float g_desc[NAT * FEAT];   // 23 MB scratch

// ---- packed fp32x2 helpers (sm_103a) ----
#define PACK2(out, lo, hi) \
    asm("mov.b64 %0, {%1, %2};" : "=l"(out) : "f"(lo), "f"(hi))
#define UNPACK2(lo, hi, v) \
    asm("mov.b64 {%0, %1}, %2;" : "=f"(lo), "=f"(hi) : "l"(v))
#define FMA2(acc, a, b) \
    asm("fma.rn.f32x2 %0, %1, %2, %0;" : "+l"(acc) : "l"(a), "l"(b))
#define MUL2(d, a, b) \
    asm("mul.rn.f32x2 %0, %1, %2;" : "=l"(d) : "l"(a), "l"(b))

typedef unsigned long long u64;

// ============================================================
// Kernel 1: per-atom descriptor (radial + angular) -> g_desc
// ============================================================
__global__ void __launch_bounds__(128, 4) atom_kernel(
    const float* __restrict__ pos,   // [NAT,3]
    const float* __restrict__ spe,   // [NAT,4]
    const float* __restrict__ theta, // [8]
    const float* __restrict__ kn,    // [1]
    const int*   __restrict__ nbr)   // [NAT,32]
{
    __shared__ float ux[NN], uy[NN], uz[NN];
    __shared__ float rn_s[NN], fc_s[NN];
    __shared__ float semb_s[NN][NEMB];
    __shared__ __align__(16) float P_s[NN][64];
    __shared__ __align__(16) float A_s[NN * NN * 8];   // [(j*32+k)*8 + t], k>=j used
    __shared__ u64 ct2_s[4], st2_s[4];                 // packed cos/sin(theta) pairs
    __shared__ __align__(16) float desc_s[FEAT];
    __shared__ float posi[3], spei[4];

    const int i   = blockIdx.x;
    const int tid = threadIdx.x;

    if (tid < 3)  posi[tid] = pos[i * 3 + tid];
    if (tid >= 4 && tid < 8) spei[tid - 4] = spe[i * 4 + (tid - 4)];
    if (tid >= 8 && tid < 12) {
        const int u = tid - 8;
        float c0 = cosf(theta[2 * u]), c1 = cosf(theta[2 * u + 1]);
        float s0 = sinf(theta[2 * u]), s1 = sinf(theta[2 * u + 1]);
        u64 cp, sp; PACK2(cp, c0, c1); PACK2(sp, s0, s1);
        ct2_s[u] = cp; st2_s[u] = sp;
    }
    for (int f = tid; f < FEAT; f += 128) desc_s[f] = 0.0f;
    __syncthreads();

    const float knv = kn[0];

    // ---- per-bond geometry, cutoff, species product ----
    if (tid < NN) {
        const int j = tid;
        const int n = nbr[i * NN + j];
        float dx = pos[n * 3 + 0] - posi[0];
        float dy = pos[n * 3 + 1] - posi[1];
        float dz = pos[n * 3 + 2] - posi[2];
        float r  = sqrtf(dx * dx + dy * dy + dz * dz) + 1e-8f;
        rn_s[j] = r;
        float inv = 1.0f / r;
        ux[j] = dx * inv; uy[j] = dy * inv; uz[j] = dz * inv;
        float fc = (r < RCUT) ? 0.5f * (cosf(PI_F * r / RCUT) + 1.0f) : 0.0f;
        fc_s[j] = fc;
        #pragma unroll
        for (int m = 0; m < 4; m++) semb_s[j][m] = spe[n * 4 + m] * spei[m];
    }
    __syncthreads();

    // ---- P[j][p] = bessel_l(r_j) * semb_m, p = l*4+m ----
    {
        const int j  = tid & 31;
        const int lg = tid >> 5;
        const float r    = rn_s[j];
        const float coef = sqrtf(2.0f / RCUT) * fc_s[j] / r;
        const float a0   = (PI_F / RCUT) * knv * r;
        const float s0 = semb_s[j][0], s1 = semb_s[j][1], s2 = semb_s[j][2], s3 = semb_s[j][3];
        #pragma unroll
        for (int li = 0; li < 4; li++) {
            const int l = lg * 4 + li;
            const float bfl = coef * sinf(a0 * (float)(l + 1));
            P_s[j][l * 4 + 0] = bfl * s0;
            P_s[j][l * 4 + 1] = bfl * s1;
            P_s[j][l * 4 + 2] = bfl * s2;
            P_s[j][l * 4 + 3] = bfl * s3;
        }
    }
    __syncthreads();

    // ---- angular weights A_t[j,k] for k >= j (packed x2 over t) ----
    {
        const u64 one2  = 0x3f8000003f800000ULL;   // (1.0f, 1.0f)
        const u64 pref2 = 0x3800000038000000ULL;   // (2^-15, 2^-15)
        for (int pi = tid; pi < NN * NN; pi += 128) {
            const int j = pi >> 5, k = pi & 31;
            if (k < j) continue;
            float c = ux[j] * ux[k] + uy[j] * uy[k] + uz[j] * uz[k];
            c = fminf(fmaxf(c, -0.999999f), 0.999999f);
            const float s = sqrtf(1.0f - c * c);
            u64 cc, ss; PACK2(cc, c, c); PACK2(ss, s, s);
            u64* a = (u64*)&A_s[pi * 8];
            #pragma unroll
            for (int u = 0; u < 4; u++) {
                u64 x = one2;
                FMA2(x, cc, ct2_s[u]);
                FMA2(x, ss, st2_s[u]);
                MUL2(x, x, x);           // x^2
                MUL2(x, x, x);           // x^4
                MUL2(x, x, x);           // x^8
                MUL2(x, x, x);           // x^16
                MUL2(x, x, pref2);
                a[u] = x;
            }
        }
    }
    __syncthreads();

    // ---- angular descriptor: ang[t][p] = sum_{j<=k} w * A_t[j,k] P[j,p] P[k,p] ----
    {
        const int p   = tid & 63;
        const int par = tid >> 6;
        u64 offd2[4] = {0, 0, 0, 0};
        u64 diag2[4] = {0, 0, 0, 0};
        for (int j = par; j < NN; j += 2) {
            const float Pj  = P_s[j][p];
            const float Pj2 = Pj * Pj;
            u64 pjj; PACK2(pjj, Pj2, Pj2);
            const ulonglong2* ad = (const ulonglong2*)&A_s[(j * 32 + j) * 8];
            ulonglong2 d0 = ad[0], d1 = ad[1];
            FMA2(diag2[0], d0.x, pjj); FMA2(diag2[1], d0.y, pjj);
            FMA2(diag2[2], d1.x, pjj); FMA2(diag2[3], d1.y, pjj);
            #pragma unroll 2
            for (int k = j + 1; k < NN; k++) {
                const float q = Pj * P_s[k][p];
                u64 qq; PACK2(qq, q, q);
                const ulonglong2* aa = (const ulonglong2*)&A_s[(j * 32 + k) * 8];
                ulonglong2 a0 = aa[0], a1 = aa[1];
                FMA2(offd2[0], a0.x, qq); FMA2(offd2[1], a0.y, qq);
                FMA2(offd2[2], a1.x, qq); FMA2(offd2[3], a1.y, qq);
            }
        }
        #pragma unroll
        for (int u = 0; u < 4; u++) {
            float dlo, dhi, olo, ohi;
            UNPACK2(dlo, dhi, diag2[u]);
            UNPACK2(olo, ohi, offd2[u]);
            atomicAdd(&desc_s[64 + (2 * u + 0) * 64 + p], dlo + 2.0f * olo);
            atomicAdd(&desc_s[64 + (2 * u + 1) * 64 + p], dhi + 2.0f * ohi);
        }

        // radial descriptor: desc_rad[p] = sum_j P[j][p]
        if (par == 0) {
            float acc = 0.0f;
            #pragma unroll
            for (int j = 0; j < NN; j++) acc += P_s[j][p];
            desc_s[p] = acc;
        }
    }
    __syncthreads();

    // ---- write descriptor to global ----
    for (int f = tid; f < FEAT; f += 128)
        g_desc[i * FEAT + f] = desc_s[f];
}

// ============================================================
// Kernel 2: batched MLP. 64 atoms / block, 256 threads.
// thread tile: 4 outputs (o0..o0+3) x 4 atoms (a0..a0+3).
// ============================================================
#define AB 64
__global__ void __launch_bounds__(256) mlp_kernel(
    const float* __restrict__ W1, const float* __restrict__ b1,
    const float* __restrict__ W2, const float* __restrict__ b2,
    const float* __restrict__ W3, const float* __restrict__ b3)
{
    __shared__ __align__(16) float bufA[64][68];   // desc chunk [f][atom]; later h2t [o][atom]
    __shared__ __align__(16) float bufB[64][68];   // h1t [o][atom]

    const int tid = threadIdx.x;
    const int oq = tid & 15, aq = tid >> 4;        // 16 x 16
    const int o0 = oq * 4, a0 = aq * 4;
    const int abase = blockIdx.x * AB;

    // ---- layer 1: h1 = tanh(desc @ W1 + b1), desc streamed in 9 chunks of 64 f ----
    u64 acc[4][2];
    #pragma unroll
    for (int a = 0; a < 4; a++) { acc[a][0] = 0; acc[a][1] = 0; }

    for (int chunk = 0; chunk < 9; chunk++) {
        const int fbase = chunk * 64;
        for (int v = tid; v < AB * 64; v += 256) {
            const int a = v >> 6, fl = v & 63;
            const int atom = abase + a;
            bufA[fl][a] = (atom < NAT) ? g_desc[atom * FEAT + fbase + fl] : 0.0f;
        }
        __syncthreads();
        #pragma unroll 4
        for (int fl = 0; fl < 64; fl++) {
            const float4 w = *(const float4*)&W1[(fbase + fl) * 64 + o0];
            u64 w01, w23; PACK2(w01, w.x, w.y); PACK2(w23, w.z, w.w);
            const float4 d = *(const float4*)&bufA[fl][a0];
            u64 dd;
            PACK2(dd, d.x, d.x); FMA2(acc[0][0], w01, dd); FMA2(acc[0][1], w23, dd);
            PACK2(dd, d.y, d.y); FMA2(acc[1][0], w01, dd); FMA2(acc[1][1], w23, dd);
            PACK2(dd, d.z, d.z); FMA2(acc[2][0], w01, dd); FMA2(acc[2][1], w23, dd);
            PACK2(dd, d.w, d.w); FMA2(acc[3][0], w01, dd); FMA2(acc[3][1], w23, dd);
        }
        __syncthreads();
    }
    {
        const float4 bb = *(const float4*)&b1[o0];
        #pragma unroll
        for (int a = 0; a < 4; a++) {
            float v0, v1, v2, v3;
            UNPACK2(v0, v1, acc[a][0]);
            UNPACK2(v2, v3, acc[a][1]);
            bufB[o0 + 0][a0 + a] = tanhf(v0 + bb.x);
            bufB[o0 + 1][a0 + a] = tanhf(v1 + bb.y);
            bufB[o0 + 2][a0 + a] = tanhf(v2 + bb.z);
            bufB[o0 + 3][a0 + a] = tanhf(v3 + bb.w);
        }
    }
    __syncthreads();

    // ---- layer 2: h2 = tanh(h1 @ W2 + b2) ----
    u64 acc2[4][2];
    #pragma unroll
    for (int a = 0; a < 4; a++) { acc2[a][0] = 0; acc2[a][1] = 0; }
    #pragma unroll 4
    for (int fl = 0; fl < 64; fl++) {
        const float4 w = *(const float4*)&W2[fl * 64 + o0];
        u64 w01, w23; PACK2(w01, w.x, w.y); PACK2(w23, w.z, w.w);
        const float4 d = *(const float4*)&bufB[fl][a0];
        u64 dd;
        PACK2(dd, d.x, d.x); FMA2(acc2[0][0], w01, dd); FMA2(acc2[0][1], w23, dd);
        PACK2(dd, d.y, d.y); FMA2(acc2[1][0], w01, dd); FMA2(acc2[1][1], w23, dd);
        PACK2(dd, d.z, d.z); FMA2(acc2[2][0], w01, dd); FMA2(acc2[2][1], w23, dd);
        PACK2(dd, d.w, d.w); FMA2(acc2[3][0], w01, dd); FMA2(acc2[3][1], w23, dd);
    }
    __syncthreads();   // bufA (desc stage) fully consumed; safe to reuse for h2t
    {
        const float4 bb = *(const float4*)&b2[o0];
        #pragma unroll
        for (int a = 0; a < 4; a++) {
            float v0, v1, v2, v3;
            UNPACK2(v0, v1, acc2[a][0]);
            UNPACK2(v2, v3, acc2[a][1]);
            bufA[o0 + 0][a0 + a] = tanhf(v0 + bb.x);
            bufA[o0 + 1][a0 + a] = tanhf(v1 + bb.y);
            bufA[o0 + 2][a0 + a] = tanhf(v2 + bb.z);
            bufA[o0 + 3][a0 + a] = tanhf(v3 + bb.w);
        }
    }
    __syncthreads();

    // ---- layer 3: e_atom = h2 @ W3 + b3 ----
    if (tid < AB) {
        float acc3 = b3[0];
        #pragma unroll 8
        for (int o = 0; o < 64; o++) acc3 += bufA[o][tid] * W3[o];
        if (abase + tid < NAT) g_eatom[abase + tid] = acc3;
    }
}

// ============================================================
// Kernel 3: deterministic fixed-order reduction
// ============================================================
__global__ void __launch_bounds__(1024) reduce_kernel(float* __restrict__ out)
{
    __shared__ double red[1024];
    const int tid = threadIdx.x;
    double acc = 0.0;
    const float4* v = (const float4*)g_eatom;   // NAT = 10000 = 2500 float4 exactly
    for (int i = tid; i < NAT / 4; i += 1024) {
        float4 x = v[i];
        acc += (double)x.x + (double)x.y + (double)x.z + (double)x.w;
    }
    red[tid] = acc;
    __syncthreads();
    for (int s = 512; s > 0; s >>= 1) {
        if (tid < s) red[tid] += red[tid + s];
        __syncthreads();
    }
    if (tid == 0) out[0] = (float)red[0];
}

extern "C" void kernel_launch(void* const* d_in, const int* in_sizes, int n_in,
                              void* d_out, int out_size)
{
    const float* pos   = (const float*)d_in[0];
    const float* spe   = (const float*)d_in[1];
    const float* theta = (const float*)d_in[2];
    const float* kn    = (const float*)d_in[3];
    const float* W1    = (const float*)d_in[4];
    const float* b1    = (const float*)d_in[5];
    const float* W2    = (const float*)d_in[6];
    const float* b2    = (const float*)d_in[7];
    const float* W3    = (const float*)d_in[8];
    const float* b3    = (const float*)d_in[9];
    const int*   nbr   = (const int*)d_in[10];

    atom_kernel<<<NAT, 128>>>(pos, spe, theta, kn, nbr);
    mlp_kernel<<<(NAT + AB - 1) / AB, 256>>>(W1, b1, W2, b2, W3, b3);
    reduce_kernel<<<1, 1024>>>((float*)d_out);
}